// round 16
// baseline (speedup 1.0000x reference)
#include <cuda_runtime.h>
#include <cuda_fp16.h>
#include <cstdint>

#define NN 50000
#define EE 400000
#define INF_ 256
#define OUTF 64
#define EDF 64
#define HH 4
#define HOUT 256   // H*OUT

// ---------------- device scratch (static, no allocs) ----------------
__device__ float g_Wb[INF_ * HOUT];      // B matrix: [n=h*64+o][k]
__device__ float g_Wi2[HOUT];
__device__ float g_Wj2[HOUT];
__device__ float g_v[HH * EDF];          // W_eatt[h] @ We[h]
__device__ float g_catt[HH];             // b_att + b_eatt . We
__device__ __half g_zh[(size_t)NN * HOUT]; // z in fp16 (only consumer: k_gather)
__device__ float g_ai[NN * HH];
__device__ float g_aj[NN * HH];
__device__ float g_ex[(size_t)EE * HH];  // exp(logit) [e][h]
__device__ float g_exc[(size_t)EE * HH]; // exp(logit) in CSR order [pos][h]
__device__ float g_segsum[NN * HH];
__device__ float g_s[(size_t)NN * HH * EDF];
// CSR
__device__ int g_deg[NN];                // zero at launch start (reset by k_scan)
__device__ int g_off[NN + 1];
__device__ int g_cur[NN];
__device__ int g_csr_src[EE];
__device__ int g_csr_eid[EE];
// decoupled-lookback scan state
__device__ volatile int g_flag[256];
__device__ volatile int g_agg[256];
__device__ volatile int g_pref[256];

__device__ __forceinline__ uint32_t tf32_of(float f) {
    uint32_t r;
    asm("cvt.rna.tf32.f32 %0, %1;" : "=r"(r) : "f"(f));
    return r;
}

__device__ __forceinline__ void mma_tf32(float* d, const uint32_t* a, const uint32_t* b) {
    asm volatile(
        "mma.sync.aligned.m16n8k8.row.col.f32.tf32.tf32.f32 "
        "{%0,%1,%2,%3}, {%4,%5,%6,%7}, {%8,%9}, {%0,%1,%2,%3};"
        : "+f"(d[0]), "+f"(d[1]), "+f"(d[2]), "+f"(d[3])
        : "r"(a[0]), "r"(a[1]), "r"(a[2]), "r"(a[3]), "r"(b[0]), "r"(b[1]));
}

__device__ __forceinline__ void red_add_f32(float* p, float v) {
    asm volatile("red.global.add.f32 [%0], %1;" :: "l"(p), "f"(v) : "memory");
}

// ---------------- K0: init + precomputes + degree histogram ----------------
__global__ void __launch_bounds__(256) k_init(
    const int* __restrict__ ei,
    const float* __restrict__ W_fc, const float* __restrict__ W_att,
    const float* __restrict__ b_att, const float* __restrict__ W_eatt,
    const float* __restrict__ b_eatt)
{
    int idx = blockIdx.x * 256 + threadIdx.x;   // 0 .. 65535
    for (int i = idx; i < NN * HH; i += 65536) {
        g_segsum[i] = 0.0f;
        g_ai[i] = 0.0f;
        g_aj[i] = 0.0f;
    }
    if (idx < 256) g_flag[idx] = 0;
    if (idx == 0) g_off[NN] = EE;
    {
        int n = idx >> 8, k = idx & 255;
        int h = n >> 6, o = n & 63;
        g_Wb[n * 256 + k] = W_fc[((size_t)h * INF_ + k) * OUTF + o];
    }
    if (idx < HOUT) {
        int h = idx / OUTF, o = idx % OUTF;
        g_Wi2[idx] = W_att[h * 192 + o];
        g_Wj2[idx] = W_att[h * 192 + 64 + o];
    }
    if (idx < HH * EDF) {
        int h = idx / EDF, f = idx % EDF;
        float s = 0.0f;
        #pragma unroll 8
        for (int g = 0; g < EDF; g++)
            s += W_eatt[((size_t)h * EDF + f) * EDF + g] * W_att[h * 192 + 128 + g];
        g_v[idx] = s;
    }
    if (idx < HH) {
        int h = idx;
        float s = b_att[h];
        for (int g = 0; g < EDF; g++)
            s += b_eatt[h * EDF + g] * W_att[h * 192 + 128 + g];
        g_catt[h] = s;
    }
    // degree histogram (g_deg is zero at launch start: module-load zero on
    // first run, reset by k_scan on every run thereafter)
    for (int e = idx; e < EE; e += 65536)
        atomicAdd(&g_deg[ei[EE + e]], 1);
}

// ---------------- K scan: single-pass decoupled-lookback exclusive scan ----------------
__global__ void __launch_bounds__(256) k_scan()
{
    __shared__ int sh[256];
    __shared__ int s_prefix;
    const int b = blockIdx.x, t = threadIdx.x;
    const int idx = b * 256 + t;
    int v = (idx < NN) ? g_deg[idx] : 0;
    if (idx < NN) g_deg[idx] = 0;   // reset for next graph replay
    sh[t] = v;
    __syncthreads();
    #pragma unroll
    for (int d = 1; d < 256; d <<= 1) {
        int x2 = (t >= d) ? sh[t - d] : 0;
        __syncthreads();
        if (t >= d) sh[t] += x2;
        __syncthreads();
    }
    if (t == 0) {
        int agg = sh[255];
        if (b == 0) {
            g_pref[0] = agg;
            __threadfence();
            g_flag[0] = 2;
            s_prefix = 0;
        } else {
            g_agg[b] = agg;
            __threadfence();
            g_flag[b] = 1;
            int prefix = 0;
            int j = b - 1;
            while (true) {
                int f;
                while ((f = g_flag[j]) == 0) { }
                __threadfence();
                if (f == 2) { prefix += g_pref[j]; break; }
                prefix += g_agg[j];
                if (--j < 0) break;
            }
            g_pref[b] = prefix + agg;
            __threadfence();
            g_flag[b] = 2;
            s_prefix = prefix;
        }
    }
    __syncthreads();
    if (idx < NN) {
        int o = s_prefix + sh[t] - v;
        g_off[idx] = o;
        g_cur[idx] = o;
    }
}

// ---------------- K1: tf32 mma.sync node GEMM: z = x @ Wb^T + b, fused ai/aj ----------------
#define KC 32
#define SSTR 132
#define STG_F (KC * SSTR)

__global__ void __launch_bounds__(256) k_node_tc(
    const float* __restrict__ x, const float* __restrict__ b_fc)
{
    extern __shared__ uint32_t smem[];
    uint32_t* As = smem;
    uint32_t* Bs = smem + 2 * STG_F;
    __shared__ float s_bias[128], s_wi[128], s_wj[128];

    const int tid = threadIdx.x;
    const int wid = tid >> 5;
    const int lane = tid & 31;
    const int wm = wid >> 2;
    const int wn = wid & 3;
    const int rowbase = blockIdx.x * 128;
    const int nbase = blockIdx.y * 128;

    const int lrow = tid >> 1;
    const int lko  = (tid & 1) * 16;

    if (tid < 128) {
        s_bias[tid] = b_fc[nbase + tid];
        s_wi[tid]   = g_Wi2[nbase + tid];
        s_wj[tid]   = g_Wj2[nbase + tid];
    }

    float acc[4][4][4];
    #pragma unroll
    for (int i = 0; i < 4; i++)
        #pragma unroll
        for (int j = 0; j < 4; j++)
            #pragma unroll
            for (int e = 0; e < 4; e++) acc[i][j][e] = 0.0f;

    float4 va[4], vb[4];

    {
        int ar = rowbase + lrow;
        #pragma unroll
        for (int j = 0; j < 4; j++) {
            va[j] = (ar < NN) ? *(const float4*)(x + (size_t)ar * INF_ + lko + j * 4)
                              : make_float4(0.f, 0.f, 0.f, 0.f);
            vb[j] = *(const float4*)(g_Wb + (size_t)(nbase + lrow) * INF_ + lko + j * 4);
        }
    }
    #pragma unroll
    for (int j = 0; j < 4; j++) {
        int k0 = lko + j * 4;
        As[(k0 + 0) * SSTR + lrow] = tf32_of(va[j].x);
        As[(k0 + 1) * SSTR + lrow] = tf32_of(va[j].y);
        As[(k0 + 2) * SSTR + lrow] = tf32_of(va[j].z);
        As[(k0 + 3) * SSTR + lrow] = tf32_of(va[j].w);
        Bs[(k0 + 0) * SSTR + lrow] = tf32_of(vb[j].x);
        Bs[(k0 + 1) * SSTR + lrow] = tf32_of(vb[j].y);
        Bs[(k0 + 2) * SSTR + lrow] = tf32_of(vb[j].z);
        Bs[(k0 + 3) * SSTR + lrow] = tf32_of(vb[j].w);
    }
    __syncthreads();

    for (int c = 0; c < 8; c++) {
        const int st = c & 1;
        const uint32_t* Ac = As + st * STG_F;
        const uint32_t* Bc = Bs + st * STG_F;

        if (c < 7) {
            int kb = (c + 1) * KC;
            int ar = rowbase + lrow;
            #pragma unroll
            for (int j = 0; j < 4; j++) {
                va[j] = (ar < NN) ? *(const float4*)(x + (size_t)ar * INF_ + kb + lko + j * 4)
                                  : make_float4(0.f, 0.f, 0.f, 0.f);
                vb[j] = *(const float4*)(g_Wb + (size_t)(nbase + lrow) * INF_ + kb + lko + j * 4);
            }
        }

        #pragma unroll
        for (int ks = 0; ks < 4; ks++) {
            uint32_t af[4][4], bf[4][2];
            const int k0 = ks * 8 + (lane & 3);
            const int mrow = wm * 64 + (lane >> 2);
            const int ncol = wn * 32 + (lane >> 2);
            #pragma unroll
            for (int mf = 0; mf < 4; mf++) {
                int m = mrow + mf * 16;
                af[mf][0] = Ac[k0 * SSTR + m];
                af[mf][1] = Ac[k0 * SSTR + m + 8];
                af[mf][2] = Ac[(k0 + 4) * SSTR + m];
                af[mf][3] = Ac[(k0 + 4) * SSTR + m + 8];
            }
            #pragma unroll
            for (int nf = 0; nf < 4; nf++) {
                int n = ncol + nf * 8;
                bf[nf][0] = Bc[k0 * SSTR + n];
                bf[nf][1] = Bc[(k0 + 4) * SSTR + n];
            }
            #pragma unroll
            for (int mf = 0; mf < 4; mf++)
                #pragma unroll
                for (int nf = 0; nf < 4; nf++)
                    mma_tf32(acc[mf][nf], af[mf], bf[nf]);
        }
        __syncthreads();

        if (c < 7) {
            uint32_t* An = As + ((c + 1) & 1) * STG_F;
            uint32_t* Bn = Bs + ((c + 1) & 1) * STG_F;
            #pragma unroll
            for (int j = 0; j < 4; j++) {
                int k0 = lko + j * 4;
                An[(k0 + 0) * SSTR + lrow] = tf32_of(va[j].x);
                An[(k0 + 1) * SSTR + lrow] = tf32_of(va[j].y);
                An[(k0 + 2) * SSTR + lrow] = tf32_of(va[j].z);
                An[(k0 + 3) * SSTR + lrow] = tf32_of(va[j].w);
                Bn[(k0 + 0) * SSTR + lrow] = tf32_of(vb[j].x);
                Bn[(k0 + 1) * SSTR + lrow] = tf32_of(vb[j].y);
                Bn[(k0 + 2) * SSTR + lrow] = tf32_of(vb[j].z);
                Bn[(k0 + 3) * SSTR + lrow] = tf32_of(vb[j].w);
            }
            __syncthreads();
        }
    }

    // epilogue: bias + store z (fp16) + fused partial ai/aj dots (fp32)
    const int hh = (nbase + wn * 32) >> 6;   // head for this warp's 32 cols
    #pragma unroll
    for (int mf = 0; mf < 4; mf++) {
        int r0 = rowbase + wm * 64 + mf * 16 + (lane >> 2);
        float si0 = 0.f, sj0 = 0.f, si1 = 0.f, sj1 = 0.f;
        #pragma unroll
        for (int nf = 0; nf < 4; nf++) {
            int cc = wn * 32 + nf * 8 + (lane & 3) * 2;
            float bx = s_bias[cc], by = s_bias[cc + 1];
            float wix = s_wi[cc], wiy = s_wi[cc + 1];
            float wjx = s_wj[cc], wjy = s_wj[cc + 1];
            float v0x = acc[mf][nf][0] + bx, v0y = acc[mf][nf][1] + by;
            float v1x = acc[mf][nf][2] + bx, v1y = acc[mf][nf][3] + by;
            si0 += v0x * wix + v0y * wiy;
            sj0 += v0x * wjx + v0y * wjy;
            si1 += v1x * wix + v1y * wiy;
            sj1 += v1x * wjx + v1y * wjy;
            if (r0 < NN)
                *(__half2*)(g_zh + (size_t)r0 * HOUT + nbase + cc) =
                    __floats2half2_rn(v0x, v0y);
            if (r0 + 8 < NN)
                *(__half2*)(g_zh + (size_t)(r0 + 8) * HOUT + nbase + cc) =
                    __floats2half2_rn(v1x, v1y);
        }
        #pragma unroll
        for (int o = 1; o <= 2; o <<= 1) {
            si0 += __shfl_xor_sync(0xffffffffu, si0, o);
            sj0 += __shfl_xor_sync(0xffffffffu, sj0, o);
            si1 += __shfl_xor_sync(0xffffffffu, si1, o);
            sj1 += __shfl_xor_sync(0xffffffffu, sj1, o);
        }
        if ((lane & 3) == 0) {
            if (r0 < NN) {
                red_add_f32(&g_ai[r0 * HH + hh], si0);
                red_add_f32(&g_aj[r0 * HH + hh], sj0);
            }
            if (r0 + 8 < NN) {
                red_add_f32(&g_ai[(r0 + 8) * HH + hh], si1);
                red_add_f32(&g_aj[(r0 + 8) * HH + hh], sj1);
            }
        }
    }
}

// ---------------- K2: edge logits (R9 shape) + exp + segsum red ----------------
__global__ void __launch_bounds__(128) k_edge_logits(
    const float* __restrict__ edge_attr, const int* __restrict__ ei)
{
    __shared__ __align__(16) float sm_ea[128 * 68];
    __shared__ __align__(16) float sm_v[HH * EDF];
    __shared__ float sm_c[HH];
    const int t = threadIdx.x;
    const int ebase = blockIdx.x * 128;

    #pragma unroll
    for (int j = 0; j < 16; j++) {
        int f4 = t + 128 * j;
        int eeI = f4 >> 4, qf = (f4 & 15) * 4;
        float4 v = *(const float4*)(edge_attr + (size_t)(ebase + eeI) * EDF + qf);
        *(float4*)(sm_ea + eeI * 68 + qf) = v;
    }
    if (t < HH * EDF) sm_v[t] = g_v[t];
    if (t + 128 < HH * EDF) sm_v[t + 128] = g_v[t + 128];
    if (t < HH) sm_c[t] = g_catt[t];
    __syncthreads();

    int ge = ebase + t;
    int src = ei[ge];
    int dst = ei[EE + ge];
    float4 ai4 = *(const float4*)(g_ai + dst * HH);
    float4 aj4 = *(const float4*)(g_aj + src * HH);
    float ain[4] = {ai4.x, ai4.y, ai4.z, ai4.w};
    float ajn[4] = {aj4.x, aj4.y, aj4.z, aj4.w};

    float exv[4];
    #pragma unroll
    for (int h = 0; h < HH; h++) {
        float acc = sm_c[h];
        #pragma unroll
        for (int f4 = 0; f4 < 16; f4++) {
            float4 ev = *(const float4*)(sm_ea + t * 68 + f4 * 4);
            float4 vv = *(const float4*)(sm_v + h * EDF + f4 * 4);
            acc += ev.x * vv.x + ev.y * vv.y + ev.z * vv.z + ev.w * vv.w;
        }
        float a = acc + ain[h] + ajn[h];
        float e = (a > 0.0f) ? a : 0.2f * a;
        exv[h] = __expf(e);
    }
    *(float4*)(g_ex + (size_t)ge * 4) =
        make_float4(exv[0], exv[1], exv[2], exv[3]);
    float* ps = g_segsum + dst * HH;
    asm volatile("red.global.add.v4.f32 [%0], {%1, %2, %3, %4};"
                 :: "l"(ps), "f"(exv[0]), "f"(exv[1]), "f"(exv[2]), "f"(exv[3])
                 : "memory");
}

// ---------------- K fill + alpha normalize/transpose + CSR-ordered ex (fused) ----------------
__global__ void __launch_bounds__(256) k_fill(
    const int* __restrict__ ei, float* __restrict__ alphaOut)
{
    int e = blockIdx.x * 256 + threadIdx.x;
    if (e >= EE) return;
    int src = ei[e];
    int dst = ei[EE + e];
    int pos = atomicAdd(&g_cur[dst], 1);
    g_csr_src[pos] = src;
    g_csr_eid[pos] = e;
    float4 a4 = *(const float4*)(g_ex + (size_t)e * 4);
    *(float4*)(g_exc + (size_t)pos * 4) = a4;
    float4 s4 = *(const float4*)(g_segsum + dst * HH);
    alphaOut[0 * (size_t)EE + e] = a4.x / s4.x;
    alphaOut[1 * (size_t)EE + e] = a4.y / s4.y;
    alphaOut[2 * (size_t)EE + e] = a4.z / s4.z;
    alphaOut[3 * (size_t)EE + e] = a4.w / s4.w;
}

// ---------------- K3: gather — fp16 z, contiguous ex, unroll 4 ----------------
__device__ __forceinline__ float4 ldz4(const __half* p) {
    uint2 u = *(const uint2*)p;
    __half2 h0 = *(__half2*)&u.x;
    __half2 h1 = *(__half2*)&u.y;
    float2 f0 = __half22float2(h0);
    float2 f1 = __half22float2(h1);
    return make_float4(f0.x, f0.y, f1.x, f1.y);
}

__global__ void __launch_bounds__(256) k_gather(
    const float* __restrict__ edge_attr, float* __restrict__ out)
{
    const int t = threadIdx.x;
    const int lane64 = t & 63;
    const int nl = t >> 6;
    const int n = blockIdx.x * 4 + nl;
    const int h = lane64 >> 4;
    const int q = lane64 & 15;

    const int beg = g_off[n];
    const int end = g_off[n + 1];

    float4 accO = make_float4(0.f, 0.f, 0.f, 0.f);
    float4 accS = make_float4(0.f, 0.f, 0.f, 0.f);
    int i = beg;
    for (; i + 3 < end; i += 4) {
        int eid0 = g_csr_eid[i],     src0 = g_csr_src[i];
        int eid1 = g_csr_eid[i + 1], src1 = g_csr_src[i + 1];
        int eid2 = g_csr_eid[i + 2], src2 = g_csr_src[i + 2];
        int eid3 = g_csr_eid[i + 3], src3 = g_csr_src[i + 3];
        float ex0 = g_exc[(size_t)i * 4 + h];
        float ex1 = g_exc[(size_t)(i + 1) * 4 + h];
        float ex2 = g_exc[(size_t)(i + 2) * 4 + h];
        float ex3 = g_exc[(size_t)(i + 3) * 4 + h];
        float4 z0 = ldz4(g_zh + (size_t)src0 * HOUT + lane64 * 4);
        float4 z1 = ldz4(g_zh + (size_t)src1 * HOUT + lane64 * 4);
        float4 z2 = ldz4(g_zh + (size_t)src2 * HOUT + lane64 * 4);
        float4 z3 = ldz4(g_zh + (size_t)src3 * HOUT + lane64 * 4);
        float4 a0 = *(const float4*)(edge_attr + (size_t)eid0 * EDF + q * 4);
        float4 a1 = *(const float4*)(edge_attr + (size_t)eid1 * EDF + q * 4);
        float4 a2 = *(const float4*)(edge_attr + (size_t)eid2 * EDF + q * 4);
        float4 a3 = *(const float4*)(edge_attr + (size_t)eid3 * EDF + q * 4);
        accO.x = fmaf(ex0, z0.x, fmaf(ex1, z1.x, fmaf(ex2, z2.x, fmaf(ex3, z3.x, accO.x))));
        accO.y = fmaf(ex0, z0.y, fmaf(ex1, z1.y, fmaf(ex2, z2.y, fmaf(ex3, z3.y, accO.y))));
        accO.z = fmaf(ex0, z0.z, fmaf(ex1, z1.z, fmaf(ex2, z2.z, fmaf(ex3, z3.z, accO.z))));
        accO.w = fmaf(ex0, z0.w, fmaf(ex1, z1.w, fmaf(ex2, z2.w, fmaf(ex3, z3.w, accO.w))));
        accS.x = fmaf(ex0, a0.x, fmaf(ex1, a1.x, fmaf(ex2, a2.x, fmaf(ex3, a3.x, accS.x))));
        accS.y = fmaf(ex0, a0.y, fmaf(ex1, a1.y, fmaf(ex2, a2.y, fmaf(ex3, a3.y, accS.y))));
        accS.z = fmaf(ex0, a0.z, fmaf(ex1, a1.z, fmaf(ex2, a2.z, fmaf(ex3, a3.z, accS.z))));
        accS.w = fmaf(ex0, a0.w, fmaf(ex1, a1.w, fmaf(ex2, a2.w, fmaf(ex3, a3.w, accS.w))));
    }
    for (; i < end; i++) {
        int eid = g_csr_eid[i], src = g_csr_src[i];
        float ex = g_exc[(size_t)i * 4 + h];
        float4 z4 = ldz4(g_zh + (size_t)src * HOUT + lane64 * 4);
        float4 e4 = *(const float4*)(edge_attr + (size_t)eid * EDF + q * 4);
        accO.x = fmaf(ex, z4.x, accO.x);
        accO.y = fmaf(ex, z4.y, accO.y);
        accO.z = fmaf(ex, z4.z, accO.z);
        accO.w = fmaf(ex, z4.w, accO.w);
        accS.x = fmaf(ex, e4.x, accS.x);
        accS.y = fmaf(ex, e4.y, accS.y);
        accS.z = fmaf(ex, e4.z, accS.z);
        accS.w = fmaf(ex, e4.w, accS.w);
    }
    float inv = (end > beg) ? 1.0f / g_segsum[n * HH + h] : 0.0f;
    accO.x *= inv; accO.y *= inv; accO.z *= inv; accO.w *= inv;
    accS.x *= inv; accS.y *= inv; accS.z *= inv; accS.w *= inv;
    *(float4*)(out + (size_t)n * HOUT + lane64 * 4) = accO;
    *(float4*)(g_s + (((size_t)n * HH + h) * EDF) + q * 4) = accS;
}

// ---------------- K5: tf32 mma out += s @ W_edge + (deg>0 ? b_edge : 0) ----------------
#define OSTR 132
#define OBSTR 68

__global__ void __launch_bounds__(256) k_out_tc(
    const float* __restrict__ W_edge, const float* __restrict__ b_edge,
    float* __restrict__ out)
{
    __shared__ uint32_t As[64 * OSTR];
    __shared__ uint32_t Bs[64 * OBSTR];
    __shared__ float s_be[64];

    const int h = blockIdx.y;
    const int rowbase = blockIdx.x * 128;
    const int tid = threadIdx.x;
    const int wid = tid >> 5;
    const int lane = tid & 31;
    const int wm = wid >> 1;
    const int wn = wid & 1;

    if (tid < 64) s_be[tid] = b_edge[h * OUTF + tid];

    {
        const int row = tid >> 1;
        const int ko = (tid & 1) * 32;
        const float* src = g_s + (((size_t)(rowbase + row) * HH + h) * EDF) + ko;
        #pragma unroll
        for (int j = 0; j < 8; j++) {
            float4 v = make_float4(0.f, 0.f, 0.f, 0.f);
            if (rowbase + row < NN) v = *(const float4*)(src + j * 4);
            int k0 = ko + j * 4;
            As[(k0 + 0) * OSTR + row] = tf32_of(v.x);
            As[(k0 + 1) * OSTR + row] = tf32_of(v.y);
            As[(k0 + 2) * OSTR + row] = tf32_of(v.z);
            As[(k0 + 3) * OSTR + row] = tf32_of(v.w);
        }
    }
    {
        const int kr = tid >> 2;
        const int qo = (tid & 3) * 16;
        const float* src = W_edge + ((size_t)h * EDF + kr) * OUTF + qo;
        #pragma unroll
        for (int j = 0; j < 4; j++) {
            float4 v = *(const float4*)(src + j * 4);
            int n0 = qo + j * 4;
            Bs[kr * OBSTR + n0 + 0] = tf32_of(v.x);
            Bs[kr * OBSTR + n0 + 1] = tf32_of(v.y);
            Bs[kr * OBSTR + n0 + 2] = tf32_of(v.z);
            Bs[kr * OBSTR + n0 + 3] = tf32_of(v.w);
        }
    }
    __syncthreads();

    float acc[2][4][4];
    #pragma unroll
    for (int i = 0; i < 2; i++)
        #pragma unroll
        for (int j = 0; j < 4; j++)
            #pragma unroll
            for (int e = 0; e < 4; e++) acc[i][j][e] = 0.0f;

    #pragma unroll
    for (int ks = 0; ks < 8; ks++) {
        uint32_t af[2][4], bf[4][2];
        const int k0 = ks * 8 + (lane & 3);
        const int mrow = wm * 32 + (lane >> 2);
        const int ncol = wn * 32 + (lane >> 2);
        #pragma unroll
        for (int mf = 0; mf < 2; mf++) {
            int m = mrow + mf * 16;
            af[mf][0] = As[k0 * OSTR + m];
            af[mf][1] = As[k0 * OSTR + m + 8];
            af[mf][2] = As[(k0 + 4) * OSTR + m];
            af[mf][3] = As[(k0 + 4) * OSTR + m + 8];
        }
        #pragma unroll
        for (int nf = 0; nf < 4; nf++) {
            int n = ncol + nf * 8;
            bf[nf][0] = Bs[k0 * OBSTR + n];
            bf[nf][1] = Bs[(k0 + 4) * OBSTR + n];
        }
        #pragma unroll
        for (int mf = 0; mf < 2; mf++)
            #pragma unroll
            for (int nf = 0; nf < 4; nf++)
                mma_tf32(acc[mf][nf], af[mf], bf[nf]);
    }

    #pragma unroll
    for (int mf = 0; mf < 2; mf++) {
        #pragma unroll
        for (int nf = 0; nf < 4; nf++) {
            int cc = wn * 32 + nf * 8 + (lane & 3) * 2;
            int r0 = rowbase + wm * 32 + mf * 16 + (lane >> 2);
            float bx = s_be[cc], by = s_be[cc + 1];
            #pragma unroll
            for (int half = 0; half < 2; half++) {
                int row = r0 + half * 8;
                if (row < NN) {
                    float flag = (g_off[row + 1] - g_off[row]) > 0 ? 1.0f : 0.0f;
                    float* po = out + (size_t)row * HOUT + h * OUTF + cc;
                    float2 o2 = *(float2*)po;
                    o2.x += acc[mf][nf][half * 2 + 0] + flag * bx;
                    o2.y += acc[mf][nf][half * 2 + 1] + flag * by;
                    *(float2*)po = o2;
                }
            }
        }
    }
}

// ---------------- launch ----------------
extern "C" void kernel_launch(void* const* d_in, const int* in_sizes, int n_in,
                              void* d_out, int out_size)
{
    const float* x      = (const float*)d_in[0];
    const int*   ei     = (const int*)d_in[1];
    const float* eattr  = (const float*)d_in[2];
    const float* W_fc   = (const float*)d_in[3];
    const float* b_fc   = (const float*)d_in[4];
    const float* W_att  = (const float*)d_in[5];
    const float* b_att  = (const float*)d_in[6];
    const float* W_edge = (const float*)d_in[7];
    const float* b_edge = (const float*)d_in[8];
    const float* W_eatt = (const float*)d_in[9];
    const float* b_eatt = (const float*)d_in[10];
    float* out = (float*)d_out;
    float* alphaOut = out + (size_t)NN * HOUT;

    const int SCAN_BLKS = (NN + 255) / 256;  // 196
    const int DYN_SMEM = 4 * STG_F * 4;

    cudaFuncSetAttribute(k_node_tc, cudaFuncAttributeMaxDynamicSharedMemorySize,
                         DYN_SMEM);

    k_init<<<256, 256>>>(ei, W_fc, W_att, b_att, W_eatt, b_eatt);
    k_scan<<<SCAN_BLKS, 256>>>();
    k_node_tc<<<dim3((NN + 127) / 128, 2), 256, DYN_SMEM>>>(x, b_fc);
    k_edge_logits<<<EE / 128, 128>>>(eattr, ei);
    k_fill<<<(EE + 255) / 256, 256>>>(ei, alphaOut);
    k_gather<<<NN / 4, 256>>>(eattr, out);
    k_out_tc<<<dim3((NN + 127) / 128, HH), 256>>>(W_edge, b_edge, out);
}

// round 17
// speedup vs baseline: 1.1077x; 1.1077x over previous
#include <cuda_runtime.h>
#include <cuda_fp16.h>
#include <cstdint>

#define NN 50000
#define EE 400000
#define INF_ 256
#define OUTF 64
#define EDF 64
#define HH 4
#define HOUT 256   // H*OUT

// ---------------- device scratch (static, no allocs) ----------------
__device__ float g_Wb[INF_ * HOUT];      // B matrix: [n=h*64+o][k]
__device__ float g_Wi2[HOUT];
__device__ float g_Wj2[HOUT];
__device__ float g_v[HH * EDF];          // W_eatt[h] @ We[h]
__device__ float g_catt[HH];             // b_att + b_eatt . We
__device__ __half g_zh[(size_t)NN * HOUT]; // z in fp16 (only consumer: k_gather)
__device__ float g_ai[NN * HH];
__device__ float g_aj[NN * HH];
__device__ float g_ex[(size_t)EE * HH];  // exp(logit) [e][h]
__device__ float g_exc[(size_t)EE * HH]; // exp(logit) in CSR order [pos][h]
__device__ float g_segsum[NN * HH];
__device__ float g_s[(size_t)NN * HH * EDF];
// CSR
__device__ int g_deg[NN];
__device__ int g_off[NN + 1];
__device__ int g_cur[NN];
__device__ int g_bsum[256];
__device__ int2 g_csr_se[EE];            // packed (src, eid)

__device__ __forceinline__ uint32_t tf32_of(float f) {
    uint32_t r;
    asm("cvt.rna.tf32.f32 %0, %1;" : "=r"(r) : "f"(f));
    return r;
}

__device__ __forceinline__ void mma_tf32(float* d, const uint32_t* a, const uint32_t* b) {
    asm volatile(
        "mma.sync.aligned.m16n8k8.row.col.f32.tf32.tf32.f32 "
        "{%0,%1,%2,%3}, {%4,%5,%6,%7}, {%8,%9}, {%0,%1,%2,%3};"
        : "+f"(d[0]), "+f"(d[1]), "+f"(d[2]), "+f"(d[3])
        : "r"(a[0]), "r"(a[1]), "r"(a[2]), "r"(a[3]), "r"(b[0]), "r"(b[1]));
}

__device__ __forceinline__ void red_add_f32(float* p, float v) {
    asm volatile("red.global.add.f32 [%0], %1;" :: "l"(p), "f"(v) : "memory");
}

// ---------------- K0: init + tiny precomputes ----------------
__global__ void __launch_bounds__(256) k_init(
    const float* __restrict__ W_fc, const float* __restrict__ W_att,
    const float* __restrict__ b_att, const float* __restrict__ W_eatt,
    const float* __restrict__ b_eatt)
{
    int idx = blockIdx.x * 256 + threadIdx.x;   // 0 .. 65535
    if (idx < NN) g_deg[idx] = 0;
    for (int i = idx; i < NN * HH; i += 65536) {
        g_segsum[i] = 0.0f;
        g_ai[i] = 0.0f;
        g_aj[i] = 0.0f;
    }
    {
        int n = idx >> 8, k = idx & 255;
        int h = n >> 6, o = n & 63;
        g_Wb[n * 256 + k] = W_fc[((size_t)h * INF_ + k) * OUTF + o];
    }
    if (idx < HOUT) {
        int h = idx / OUTF, o = idx % OUTF;
        g_Wi2[idx] = W_att[h * 192 + o];
        g_Wj2[idx] = W_att[h * 192 + 64 + o];
    }
    if (idx < HH * EDF) {
        int h = idx / EDF, f = idx % EDF;
        float s = 0.0f;
        #pragma unroll 8
        for (int g = 0; g < EDF; g++)
            s += W_eatt[((size_t)h * EDF + f) * EDF + g] * W_att[h * 192 + 128 + g];
        g_v[idx] = s;
    }
    if (idx < HH) {
        int h = idx;
        float s = b_att[h];
        for (int g = 0; g < EDF; g++)
            s += b_eatt[h * EDF + g] * W_att[h * 192 + 128 + g];
        g_catt[h] = s;
    }
}

// ---------------- K1: tf32 mma.sync node GEMM: z = x @ Wb^T + b, fused ai/aj ----------------
#define KC 32
#define SSTR 132
#define STG_F (KC * SSTR)

__global__ void __launch_bounds__(256) k_node_tc(
    const float* __restrict__ x, const float* __restrict__ b_fc)
{
    extern __shared__ uint32_t smem[];
    uint32_t* As = smem;
    uint32_t* Bs = smem + 2 * STG_F;
    __shared__ float s_bias[128], s_wi[128], s_wj[128];

    const int tid = threadIdx.x;
    const int wid = tid >> 5;
    const int lane = tid & 31;
    const int wm = wid >> 2;
    const int wn = wid & 3;
    const int rowbase = blockIdx.x * 128;
    const int nbase = blockIdx.y * 128;

    const int lrow = tid >> 1;
    const int lko  = (tid & 1) * 16;

    if (tid < 128) {
        s_bias[tid] = b_fc[nbase + tid];
        s_wi[tid]   = g_Wi2[nbase + tid];
        s_wj[tid]   = g_Wj2[nbase + tid];
    }

    float acc[4][4][4];
    #pragma unroll
    for (int i = 0; i < 4; i++)
        #pragma unroll
        for (int j = 0; j < 4; j++)
            #pragma unroll
            for (int e = 0; e < 4; e++) acc[i][j][e] = 0.0f;

    float4 va[4], vb[4];

    {
        int ar = rowbase + lrow;
        #pragma unroll
        for (int j = 0; j < 4; j++) {
            va[j] = (ar < NN) ? *(const float4*)(x + (size_t)ar * INF_ + lko + j * 4)
                              : make_float4(0.f, 0.f, 0.f, 0.f);
            vb[j] = *(const float4*)(g_Wb + (size_t)(nbase + lrow) * INF_ + lko + j * 4);
        }
    }
    #pragma unroll
    for (int j = 0; j < 4; j++) {
        int k0 = lko + j * 4;
        As[(k0 + 0) * SSTR + lrow] = tf32_of(va[j].x);
        As[(k0 + 1) * SSTR + lrow] = tf32_of(va[j].y);
        As[(k0 + 2) * SSTR + lrow] = tf32_of(va[j].z);
        As[(k0 + 3) * SSTR + lrow] = tf32_of(va[j].w);
        Bs[(k0 + 0) * SSTR + lrow] = tf32_of(vb[j].x);
        Bs[(k0 + 1) * SSTR + lrow] = tf32_of(vb[j].y);
        Bs[(k0 + 2) * SSTR + lrow] = tf32_of(vb[j].z);
        Bs[(k0 + 3) * SSTR + lrow] = tf32_of(vb[j].w);
    }
    __syncthreads();

    for (int c = 0; c < 8; c++) {
        const int st = c & 1;
        const uint32_t* Ac = As + st * STG_F;
        const uint32_t* Bc = Bs + st * STG_F;

        if (c < 7) {
            int kb = (c + 1) * KC;
            int ar = rowbase + lrow;
            #pragma unroll
            for (int j = 0; j < 4; j++) {
                va[j] = (ar < NN) ? *(const float4*)(x + (size_t)ar * INF_ + kb + lko + j * 4)
                                  : make_float4(0.f, 0.f, 0.f, 0.f);
                vb[j] = *(const float4*)(g_Wb + (size_t)(nbase + lrow) * INF_ + kb + lko + j * 4);
            }
        }

        #pragma unroll
        for (int ks = 0; ks < 4; ks++) {
            uint32_t af[4][4], bf[4][2];
            const int k0 = ks * 8 + (lane & 3);
            const int mrow = wm * 64 + (lane >> 2);
            const int ncol = wn * 32 + (lane >> 2);
            #pragma unroll
            for (int mf = 0; mf < 4; mf++) {
                int m = mrow + mf * 16;
                af[mf][0] = Ac[k0 * SSTR + m];
                af[mf][1] = Ac[k0 * SSTR + m + 8];
                af[mf][2] = Ac[(k0 + 4) * SSTR + m];
                af[mf][3] = Ac[(k0 + 4) * SSTR + m + 8];
            }
            #pragma unroll
            for (int nf = 0; nf < 4; nf++) {
                int n = ncol + nf * 8;
                bf[nf][0] = Bc[k0 * SSTR + n];
                bf[nf][1] = Bc[(k0 + 4) * SSTR + n];
            }
            #pragma unroll
            for (int mf = 0; mf < 4; mf++)
                #pragma unroll
                for (int nf = 0; nf < 4; nf++)
                    mma_tf32(acc[mf][nf], af[mf], bf[nf]);
        }
        __syncthreads();

        if (c < 7) {
            uint32_t* An = As + ((c + 1) & 1) * STG_F;
            uint32_t* Bn = Bs + ((c + 1) & 1) * STG_F;
            #pragma unroll
            for (int j = 0; j < 4; j++) {
                int k0 = lko + j * 4;
                An[(k0 + 0) * SSTR + lrow] = tf32_of(va[j].x);
                An[(k0 + 1) * SSTR + lrow] = tf32_of(va[j].y);
                An[(k0 + 2) * SSTR + lrow] = tf32_of(va[j].z);
                An[(k0 + 3) * SSTR + lrow] = tf32_of(va[j].w);
                Bn[(k0 + 0) * SSTR + lrow] = tf32_of(vb[j].x);
                Bn[(k0 + 1) * SSTR + lrow] = tf32_of(vb[j].y);
                Bn[(k0 + 2) * SSTR + lrow] = tf32_of(vb[j].z);
                Bn[(k0 + 3) * SSTR + lrow] = tf32_of(vb[j].w);
            }
            __syncthreads();
        }
    }

    // epilogue: bias + store z (fp16) + fused partial ai/aj dots (fp32)
    const int hh = (nbase + wn * 32) >> 6;   // head for this warp's 32 cols
    #pragma unroll
    for (int mf = 0; mf < 4; mf++) {
        int r0 = rowbase + wm * 64 + mf * 16 + (lane >> 2);
        float si0 = 0.f, sj0 = 0.f, si1 = 0.f, sj1 = 0.f;
        #pragma unroll
        for (int nf = 0; nf < 4; nf++) {
            int cc = wn * 32 + nf * 8 + (lane & 3) * 2;
            float bx = s_bias[cc], by = s_bias[cc + 1];
            float wix = s_wi[cc], wiy = s_wi[cc + 1];
            float wjx = s_wj[cc], wjy = s_wj[cc + 1];
            float v0x = acc[mf][nf][0] + bx, v0y = acc[mf][nf][1] + by;
            float v1x = acc[mf][nf][2] + bx, v1y = acc[mf][nf][3] + by;
            si0 += v0x * wix + v0y * wiy;
            sj0 += v0x * wjx + v0y * wjy;
            si1 += v1x * wix + v1y * wiy;
            sj1 += v1x * wjx + v1y * wjy;
            if (r0 < NN)
                *(__half2*)(g_zh + (size_t)r0 * HOUT + nbase + cc) =
                    __floats2half2_rn(v0x, v0y);
            if (r0 + 8 < NN)
                *(__half2*)(g_zh + (size_t)(r0 + 8) * HOUT + nbase + cc) =
                    __floats2half2_rn(v1x, v1y);
        }
        #pragma unroll
        for (int o = 1; o <= 2; o <<= 1) {
            si0 += __shfl_xor_sync(0xffffffffu, si0, o);
            sj0 += __shfl_xor_sync(0xffffffffu, sj0, o);
            si1 += __shfl_xor_sync(0xffffffffu, si1, o);
            sj1 += __shfl_xor_sync(0xffffffffu, sj1, o);
        }
        if ((lane & 3) == 0) {
            if (r0 < NN) {
                red_add_f32(&g_ai[r0 * HH + hh], si0);
                red_add_f32(&g_aj[r0 * HH + hh], sj0);
            }
            if (r0 + 8 < NN) {
                red_add_f32(&g_ai[(r0 + 8) * HH + hh], si1);
                red_add_f32(&g_aj[(r0 + 8) * HH + hh], sj1);
            }
        }
    }
}

// ---------------- K2: edge logits (R9 shape) + exp + segsum red + deg ----------------
__global__ void __launch_bounds__(128) k_edge_logits(
    const float* __restrict__ edge_attr, const int* __restrict__ ei)
{
    __shared__ __align__(16) float sm_ea[128 * 68];
    __shared__ __align__(16) float sm_v[HH * EDF];
    __shared__ float sm_c[HH];
    const int t = threadIdx.x;
    const int ebase = blockIdx.x * 128;

    #pragma unroll
    for (int j = 0; j < 16; j++) {
        int f4 = t + 128 * j;
        int eeI = f4 >> 4, qf = (f4 & 15) * 4;
        float4 v = *(const float4*)(edge_attr + (size_t)(ebase + eeI) * EDF + qf);
        *(float4*)(sm_ea + eeI * 68 + qf) = v;
    }
    if (t < HH * EDF) sm_v[t] = g_v[t];
    if (t + 128 < HH * EDF) sm_v[t + 128] = g_v[t + 128];
    if (t < HH) sm_c[t] = g_catt[t];
    __syncthreads();

    int ge = ebase + t;
    int src = ei[ge];
    int dst = ei[EE + ge];
    float4 ai4 = *(const float4*)(g_ai + dst * HH);
    float4 aj4 = *(const float4*)(g_aj + src * HH);
    float ain[4] = {ai4.x, ai4.y, ai4.z, ai4.w};
    float ajn[4] = {aj4.x, aj4.y, aj4.z, aj4.w};

    float exv[4];
    #pragma unroll
    for (int h = 0; h < HH; h++) {
        float acc = sm_c[h];
        #pragma unroll
        for (int f4 = 0; f4 < 16; f4++) {
            float4 ev = *(const float4*)(sm_ea + t * 68 + f4 * 4);
            float4 vv = *(const float4*)(sm_v + h * EDF + f4 * 4);
            acc += ev.x * vv.x + ev.y * vv.y + ev.z * vv.z + ev.w * vv.w;
        }
        float a = acc + ain[h] + ajn[h];
        float e = (a > 0.0f) ? a : 0.2f * a;
        exv[h] = __expf(e);
    }
    *(float4*)(g_ex + (size_t)ge * 4) =
        make_float4(exv[0], exv[1], exv[2], exv[3]);
    float* ps = g_segsum + dst * HH;
    asm volatile("red.global.add.v4.f32 [%0], {%1, %2, %3, %4};"
                 :: "l"(ps), "f"(exv[0]), "f"(exv[1]), "f"(exv[2]), "f"(exv[3])
                 : "memory");
    atomicAdd(&g_deg[dst], 1);
}

// ---------------- CSR build: 3-stage scan ----------------
__global__ void __launch_bounds__(256) k_scan_a()
{
    __shared__ int sh[256];
    int t = threadIdx.x;
    int idx = blockIdx.x * 256 + t;
    int v = (idx < NN) ? g_deg[idx] : 0;
    sh[t] = v;
    __syncthreads();
    #pragma unroll
    for (int d = 1; d < 256; d <<= 1) {
        int x = (t >= d) ? sh[t - d] : 0;
        __syncthreads();
        if (t >= d) sh[t] += x;
        __syncthreads();
    }
    if (idx < NN) g_off[idx] = sh[t] - v;
    if (t == 255) g_bsum[blockIdx.x] = sh[255];
}

__global__ void __launch_bounds__(256) k_scan_b(int nblocks)
{
    __shared__ int sh[256];
    int t = threadIdx.x;
    int v = (t < nblocks) ? g_bsum[t] : 0;
    sh[t] = v;
    __syncthreads();
    #pragma unroll
    for (int d = 1; d < 256; d <<= 1) {
        int x = (t >= d) ? sh[t - d] : 0;
        __syncthreads();
        if (t >= d) sh[t] += x;
        __syncthreads();
    }
    if (t < nblocks) g_bsum[t] = sh[t] - v;
}

__global__ void __launch_bounds__(256) k_scan_c()
{
    int idx = blockIdx.x * 256 + threadIdx.x;
    if (idx < NN) {
        int o = g_off[idx] + g_bsum[blockIdx.x];
        g_off[idx] = o;
        g_cur[idx] = o;
    }
    if (idx == 0) g_off[NN] = EE;
}

// ---------------- K fill + alpha normalize/transpose + CSR-ordered ex (fused) ----------------
__global__ void __launch_bounds__(256) k_fill(
    const int* __restrict__ ei, float* __restrict__ alphaOut)
{
    int e = blockIdx.x * 256 + threadIdx.x;
    if (e >= EE) return;
    int src = ei[e];
    int dst = ei[EE + e];
    int pos = atomicAdd(&g_cur[dst], 1);
    g_csr_se[pos] = make_int2(src, e);
    float4 a4 = *(const float4*)(g_ex + (size_t)e * 4);
    *(float4*)(g_exc + (size_t)pos * 4) = a4;
    float4 s4 = *(const float4*)(g_segsum + dst * HH);
    alphaOut[0 * (size_t)EE + e] = a4.x / s4.x;
    alphaOut[1 * (size_t)EE + e] = a4.y / s4.y;
    alphaOut[2 * (size_t)EE + e] = a4.z / s4.z;
    alphaOut[3 * (size_t)EE + e] = a4.w / s4.w;
}

// ---------------- K3: gather — fp16 z (ldg), packed CSR, contiguous ex, unroll 4 ----------------
__device__ __forceinline__ float4 ldz4(const __half* p) {
    uint2 u = __ldg((const uint2*)p);
    __half2 h0 = *(__half2*)&u.x;
    __half2 h1 = *(__half2*)&u.y;
    float2 f0 = __half22float2(h0);
    float2 f1 = __half22float2(h1);
    return make_float4(f0.x, f0.y, f1.x, f1.y);
}

__global__ void __launch_bounds__(256) k_gather(
    const float* __restrict__ edge_attr, float* __restrict__ out)
{
    const int t = threadIdx.x;
    const int lane64 = t & 63;
    const int nl = t >> 6;
    const int n = blockIdx.x * 4 + nl;
    const int h = lane64 >> 4;
    const int q = lane64 & 15;

    const int beg = g_off[n];
    const int end = g_off[n + 1];

    float4 accO = make_float4(0.f, 0.f, 0.f, 0.f);
    float4 accS = make_float4(0.f, 0.f, 0.f, 0.f);
    int i = beg;
    for (; i + 3 < end; i += 4) {
        int2 se0 = g_csr_se[i];
        int2 se1 = g_csr_se[i + 1];
        int2 se2 = g_csr_se[i + 2];
        int2 se3 = g_csr_se[i + 3];
        float ex0 = g_exc[(size_t)i * 4 + h];
        float ex1 = g_exc[(size_t)(i + 1) * 4 + h];
        float ex2 = g_exc[(size_t)(i + 2) * 4 + h];
        float ex3 = g_exc[(size_t)(i + 3) * 4 + h];
        float4 z0 = ldz4(g_zh + (size_t)se0.x * HOUT + lane64 * 4);
        float4 z1 = ldz4(g_zh + (size_t)se1.x * HOUT + lane64 * 4);
        float4 z2 = ldz4(g_zh + (size_t)se2.x * HOUT + lane64 * 4);
        float4 z3 = ldz4(g_zh + (size_t)se3.x * HOUT + lane64 * 4);
        float4 a0 = *(const float4*)(edge_attr + (size_t)se0.y * EDF + q * 4);
        float4 a1 = *(const float4*)(edge_attr + (size_t)se1.y * EDF + q * 4);
        float4 a2 = *(const float4*)(edge_attr + (size_t)se2.y * EDF + q * 4);
        float4 a3 = *(const float4*)(edge_attr + (size_t)se3.y * EDF + q * 4);
        accO.x = fmaf(ex0, z0.x, fmaf(ex1, z1.x, fmaf(ex2, z2.x, fmaf(ex3, z3.x, accO.x))));
        accO.y = fmaf(ex0, z0.y, fmaf(ex1, z1.y, fmaf(ex2, z2.y, fmaf(ex3, z3.y, accO.y))));
        accO.z = fmaf(ex0, z0.z, fmaf(ex1, z1.z, fmaf(ex2, z2.z, fmaf(ex3, z3.z, accO.z))));
        accO.w = fmaf(ex0, z0.w, fmaf(ex1, z1.w, fmaf(ex2, z2.w, fmaf(ex3, z3.w, accO.w))));
        accS.x = fmaf(ex0, a0.x, fmaf(ex1, a1.x, fmaf(ex2, a2.x, fmaf(ex3, a3.x, accS.x))));
        accS.y = fmaf(ex0, a0.y, fmaf(ex1, a1.y, fmaf(ex2, a2.y, fmaf(ex3, a3.y, accS.y))));
        accS.z = fmaf(ex0, a0.z, fmaf(ex1, a1.z, fmaf(ex2, a2.z, fmaf(ex3, a3.z, accS.z))));
        accS.w = fmaf(ex0, a0.w, fmaf(ex1, a1.w, fmaf(ex2, a2.w, fmaf(ex3, a3.w, accS.w))));
    }
    for (; i < end; i++) {
        int2 se = g_csr_se[i];
        float ex = g_exc[(size_t)i * 4 + h];
        float4 z4 = ldz4(g_zh + (size_t)se.x * HOUT + lane64 * 4);
        float4 e4 = *(const float4*)(edge_attr + (size_t)se.y * EDF + q * 4);
        accO.x = fmaf(ex, z4.x, accO.x);
        accO.y = fmaf(ex, z4.y, accO.y);
        accO.z = fmaf(ex, z4.z, accO.z);
        accO.w = fmaf(ex, z4.w, accO.w);
        accS.x = fmaf(ex, e4.x, accS.x);
        accS.y = fmaf(ex, e4.y, accS.y);
        accS.z = fmaf(ex, e4.z, accS.z);
        accS.w = fmaf(ex, e4.w, accS.w);
    }
    float inv = (end > beg) ? 1.0f / g_segsum[n * HH + h] : 0.0f;
    accO.x *= inv; accO.y *= inv; accO.z *= inv; accO.w *= inv;
    accS.x *= inv; accS.y *= inv; accS.z *= inv; accS.w *= inv;
    *(float4*)(out + (size_t)n * HOUT + lane64 * 4) = accO;
    *(float4*)(g_s + (((size_t)n * HH + h) * EDF) + q * 4) = accS;
}

// ---------------- K5: tf32 mma out += s @ W_edge + (deg>0 ? b_edge : 0) ----------------
#define OSTR 132
#define OBSTR 68

__global__ void __launch_bounds__(256) k_out_tc(
    const float* __restrict__ W_edge, const float* __restrict__ b_edge,
    float* __restrict__ out)
{
    __shared__ uint32_t As[64 * OSTR];
    __shared__ uint32_t Bs[64 * OBSTR];
    __shared__ float s_be[64];

    const int h = blockIdx.y;
    const int rowbase = blockIdx.x * 128;
    const int tid = threadIdx.x;
    const int wid = tid >> 5;
    const int lane = tid & 31;
    const int wm = wid >> 1;
    const int wn = wid & 1;

    if (tid < 64) s_be[tid] = b_edge[h * OUTF + tid];

    {
        const int row = tid >> 1;
        const int ko = (tid & 1) * 32;
        const float* src = g_s + (((size_t)(rowbase + row) * HH + h) * EDF) + ko;
        #pragma unroll
        for (int j = 0; j < 8; j++) {
            float4 v = make_float4(0.f, 0.f, 0.f, 0.f);
            if (rowbase + row < NN) v = *(const float4*)(src + j * 4);
            int k0 = ko + j * 4;
            As[(k0 + 0) * OSTR + row] = tf32_of(v.x);
            As[(k0 + 1) * OSTR + row] = tf32_of(v.y);
            As[(k0 + 2) * OSTR + row] = tf32_of(v.z);
            As[(k0 + 3) * OSTR + row] = tf32_of(v.w);
        }
    }
    {
        const int kr = tid >> 2;
        const int qo = (tid & 3) * 16;
        const float* src = W_edge + ((size_t)h * EDF + kr) * OUTF + qo;
        #pragma unroll
        for (int j = 0; j < 4; j++) {
            float4 v = *(const float4*)(src + j * 4);
            int n0 = qo + j * 4;
            Bs[kr * OBSTR + n0 + 0] = tf32_of(v.x);
            Bs[kr * OBSTR + n0 + 1] = tf32_of(v.y);
            Bs[kr * OBSTR + n0 + 2] = tf32_of(v.z);
            Bs[kr * OBSTR + n0 + 3] = tf32_of(v.w);
        }
    }
    __syncthreads();

    float acc[2][4][4];
    #pragma unroll
    for (int i = 0; i < 2; i++)
        #pragma unroll
        for (int j = 0; j < 4; j++)
            #pragma unroll
            for (int e = 0; e < 4; e++) acc[i][j][e] = 0.0f;

    #pragma unroll
    for (int ks = 0; ks < 8; ks++) {
        uint32_t af[2][4], bf[4][2];
        const int k0 = ks * 8 + (lane & 3);
        const int mrow = wm * 32 + (lane >> 2);
        const int ncol = wn * 32 + (lane >> 2);
        #pragma unroll
        for (int mf = 0; mf < 2; mf++) {
            int m = mrow + mf * 16;
            af[mf][0] = As[k0 * OSTR + m];
            af[mf][1] = As[k0 * OSTR + m + 8];
            af[mf][2] = As[(k0 + 4) * OSTR + m];
            af[mf][3] = As[(k0 + 4) * OSTR + m + 8];
        }
        #pragma unroll
        for (int nf = 0; nf < 4; nf++) {
            int n = ncol + nf * 8;
            bf[nf][0] = Bs[k0 * OBSTR + n];
            bf[nf][1] = Bs[(k0 + 4) * OBSTR + n];
        }
        #pragma unroll
        for (int mf = 0; mf < 2; mf++)
            #pragma unroll
            for (int nf = 0; nf < 4; nf++)
                mma_tf32(acc[mf][nf], af[mf], bf[nf]);
    }

    #pragma unroll
    for (int mf = 0; mf < 2; mf++) {
        #pragma unroll
        for (int nf = 0; nf < 4; nf++) {
            int cc = wn * 32 + nf * 8 + (lane & 3) * 2;
            int r0 = rowbase + wm * 32 + mf * 16 + (lane >> 2);
            float bx = s_be[cc], by = s_be[cc + 1];
            #pragma unroll
            for (int half = 0; half < 2; half++) {
                int row = r0 + half * 8;
                if (row < NN) {
                    float flag = (g_off[row + 1] - g_off[row]) > 0 ? 1.0f : 0.0f;
                    float* po = out + (size_t)row * HOUT + h * OUTF + cc;
                    float2 o2 = *(float2*)po;
                    o2.x += acc[mf][nf][half * 2 + 0] + flag * bx;
                    o2.y += acc[mf][nf][half * 2 + 1] + flag * by;
                    *(float2*)po = o2;
                }
            }
        }
    }
}

// ---------------- launch ----------------
extern "C" void kernel_launch(void* const* d_in, const int* in_sizes, int n_in,
                              void* d_out, int out_size)
{
    const float* x      = (const float*)d_in[0];
    const int*   ei     = (const int*)d_in[1];
    const float* eattr  = (const float*)d_in[2];
    const float* W_fc   = (const float*)d_in[3];
    const float* b_fc   = (const float*)d_in[4];
    const float* W_att  = (const float*)d_in[5];
    const float* b_att  = (const float*)d_in[6];
    const float* W_edge = (const float*)d_in[7];
    const float* b_edge = (const float*)d_in[8];
    const float* W_eatt = (const float*)d_in[9];
    const float* b_eatt = (const float*)d_in[10];
    float* out = (float*)d_out;
    float* alphaOut = out + (size_t)NN * HOUT;

    const int SCAN_BLKS = (NN + 255) / 256;  // 196
    const int DYN_SMEM = 4 * STG_F * 4;

    cudaFuncSetAttribute(k_node_tc, cudaFuncAttributeMaxDynamicSharedMemorySize,
                         DYN_SMEM);

    k_init<<<256, 256>>>(W_fc, W_att, b_att, W_eatt, b_eatt);
    k_node_tc<<<dim3((NN + 127) / 128, 2), 256, DYN_SMEM>>>(x, b_fc);
    k_edge_logits<<<EE / 128, 128>>>(eattr, ei);
    k_scan_a<<<SCAN_BLKS, 256>>>();
    k_scan_b<<<1, 256>>>(SCAN_BLKS);
    k_scan_c<<<SCAN_BLKS, 256>>>();
    k_fill<<<(EE + 255) / 256, 256>>>(ei, alphaOut);
    k_gather<<<NN / 4, 256>>>(eattr, out);
    k_out_tc<<<dim3((NN + 127) / 128, HH), 256>>>(W_edge, b_edge, out);
}